// round 1
// baseline (speedup 1.0000x reference)
#include <cuda_runtime.h>
#include <cuda_bf16.h>
#include <cstdio>

// Problem constants (fixed shapes per reference)
#define N_NODES 50000
#define N_EDGES 600000
#define NRELS   8
#define F       128

// ---------------- scratch (static device globals; no allocation) ------------
__device__ float g_hrel[(size_t)NRELS * N_NODES * F];   // [R][N][F] ~205 MB
__device__ float g_gate[NRELS * N_NODES];               // sigmoid(gate) [R][N]
__device__ int   g_cnt[N_NODES];
__device__ int   g_off[N_NODES + 1];
__device__ int   g_cursor[N_NODES];
__device__ int   g_eidx[N_EDGES];

// ---------------- CSR build ------------------------------------------------
__global__ void zero_cnt_k() {
    int i = blockIdx.x * blockDim.x + threadIdx.x;
    if (i < N_NODES) g_cnt[i] = 0;
}

__global__ void count_k(const int* __restrict__ dst) {
    int i = blockIdx.x * blockDim.x + threadIdx.x;
    if (i < N_EDGES) atomicAdd(&g_cnt[dst[i]], 1);
}

// single-block exclusive scan over 50000 counts
__global__ void scan_k() {
    __shared__ int wsum[32];
    __shared__ int carry_s;
    int t = threadIdx.x;
    if (t == 0) carry_s = 0;
    __syncthreads();
    for (int base = 0; base < N_NODES; base += 1024) {
        int i = base + t;
        int v = (i < N_NODES) ? g_cnt[i] : 0;
        int x = v;  // inclusive scan within warp
        #pragma unroll
        for (int d = 1; d < 32; d <<= 1) {
            int y = __shfl_up_sync(0xffffffffu, x, d);
            if ((t & 31) >= d) x += y;
        }
        if ((t & 31) == 31) wsum[t >> 5] = x;
        __syncthreads();
        if (t < 32) {
            int y = wsum[t];
            int z = y;
            #pragma unroll
            for (int d = 1; d < 32; d <<= 1) {
                int u = __shfl_up_sync(0xffffffffu, z, d);
                if (t >= d) z += u;
            }
            wsum[t] = z - y;   // exclusive warp offsets
        }
        __syncthreads();
        int excl = x - v + wsum[t >> 5];
        int off = carry_s + excl;
        if (i < N_NODES) { g_off[i] = off; g_cursor[i] = off; }
        __syncthreads();   // everyone has read carry_s
        if (t == 1023) carry_s = off + v;  // inclusive total of this chunk
        __syncthreads();
    }
    if (t == 0) g_off[N_NODES] = carry_s;
}

__global__ void fill_k(const int* __restrict__ dst) {
    int i = blockIdx.x * blockDim.x + threadIdx.x;
    if (i < N_EDGES) {
        int p = atomicAdd(&g_cursor[dst[i]], 1);
        g_eidx[p] = i;
    }
}

// ---------------- gate: sigmoid(h . gate_w[r]) per (r, node) ---------------
__global__ void gate_k(const float* __restrict__ h, const float* __restrict__ gw) {
    int w = (blockIdx.x * blockDim.x + threadIdx.x) >> 5;   // node (warp per node)
    int lane = threadIdx.x & 31;
    if (w >= N_NODES) return;
    float4 hv = ((const float4*)h)[(size_t)w * 32 + lane];
    #pragma unroll
    for (int r = 0; r < NRELS; r++) {
        float4 g4 = ((const float4*)gw)[r * 32 + lane];
        float p = hv.x * g4.x + hv.y * g4.y + hv.z * g4.z + hv.w * g4.w;
        #pragma unroll
        for (int d = 16; d; d >>= 1) p += __shfl_xor_sync(0xffffffffu, p, d);
        if (lane == 0) g_gate[r * N_NODES + w] = 1.0f / (1.0f + __expf(-p));
    }
}

// ---------------- GEMM: h @ W_r -> g_hrel ; r==8: h @ loop_w + bias -> out --
// 128x128 tile per block, 256 threads, 8x8 micro-tile, whole K=128 in smem.
#define SMEM_FLOATS (128 * 132 + 128 * 128)

__global__ void __launch_bounds__(256) gemm_k(
    const float* __restrict__ h, const float* __restrict__ weight,
    const float* __restrict__ loopw, const float* __restrict__ bias,
    float* __restrict__ out)
{
    extern __shared__ float sm[];
    float* As = sm;                  // [128][132] padded
    float* Bs = sm + 128 * 132;      // [128][128]  (k-major, W layout)
    int r = blockIdx.y;
    int nodeBase = blockIdx.x * 128;
    const float* W = (r < NRELS) ? (weight + (size_t)r * F * F) : loopw;

    // load W (16384 floats)
    for (int i = threadIdx.x; i < (F * F) / 4; i += 256)
        ((float4*)Bs)[i] = ((const float4*)W)[i];
    // load A tile (128 rows x 128 cols), zero-pad out-of-range rows
    for (int i = threadIdx.x; i < (128 * F) / 4; i += 256) {
        int m = i >> 5, kc = i & 31;
        int row = nodeBase + m;
        float4 v = (row < N_NODES) ? ((const float4*)h)[(size_t)row * 32 + kc]
                                   : make_float4(0.f, 0.f, 0.f, 0.f);
        *(float4*)(As + m * 132 + kc * 4) = v;
    }
    __syncthreads();

    int tx = threadIdx.x & 15, ty = threadIdx.x >> 4;
    float acc[8][8];
    #pragma unroll
    for (int i = 0; i < 8; i++)
        #pragma unroll
        for (int j = 0; j < 8; j++) acc[i][j] = 0.f;

    const float* Arow = As + (ty * 8) * 132;
    #pragma unroll 8
    for (int k = 0; k < 128; k++) {
        float a[8], b[8];
        #pragma unroll
        for (int i = 0; i < 8; i++) a[i] = Arow[i * 132 + k];
        *(float4*)(b)     = *(const float4*)(Bs + k * 128 + tx * 8);
        *(float4*)(b + 4) = *(const float4*)(Bs + k * 128 + tx * 8 + 4);
        #pragma unroll
        for (int mi = 0; mi < 8; mi++)
            #pragma unroll
            for (int ni = 0; ni < 8; ni++)
                acc[mi][ni] += a[mi] * b[ni];
    }

    if (r < NRELS) {
        float* dp = g_hrel + ((size_t)r * N_NODES + nodeBase) * F;
        #pragma unroll
        for (int mi = 0; mi < 8; mi++) {
            int row = ty * 8 + mi;
            if (nodeBase + row < N_NODES) {
                *(float4*)(dp + (size_t)row * F + tx * 8)     = *(float4*)(&acc[mi][0]);
                *(float4*)(dp + (size_t)row * F + tx * 8 + 4) = *(float4*)(&acc[mi][4]);
            }
        }
    } else {
        float4 b0 = *(const float4*)(bias + tx * 8);
        float4 b1 = *(const float4*)(bias + tx * 8 + 4);
        #pragma unroll
        for (int mi = 0; mi < 8; mi++) {
            int row = ty * 8 + mi;
            if (nodeBase + row < N_NODES) {
                float4 v0, v1;
                v0.x = acc[mi][0] + b0.x; v0.y = acc[mi][1] + b0.y;
                v0.z = acc[mi][2] + b0.z; v0.w = acc[mi][3] + b0.w;
                v1.x = acc[mi][4] + b1.x; v1.y = acc[mi][5] + b1.y;
                v1.z = acc[mi][6] + b1.z; v1.w = acc[mi][7] + b1.w;
                *(float4*)(out + (size_t)(nodeBase + row) * F + tx * 8)     = v0;
                *(float4*)(out + (size_t)(nodeBase + row) * F + tx * 8 + 4) = v1;
            }
        }
    }
}

// ---------------- aggregate: warp per dst node, CSR gather, fused ReLU -----
__global__ void __launch_bounds__(256) agg_k(
    const float* __restrict__ norm, const int* __restrict__ src,
    const int* __restrict__ rel, float* __restrict__ out)
{
    int w = (blockIdx.x * 256 + threadIdx.x) >> 5;   // node
    int lane = threadIdx.x & 31;
    int beg = g_off[w], end = g_off[w + 1];
    float4 acc = make_float4(0.f, 0.f, 0.f, 0.f);
    for (int j0 = beg; j0 < end; j0 += 32) {
        int cnt = min(32, end - j0);
        int myIdx = 0; float myC = 0.f;
        if (lane < cnt) {
            int e = g_eidx[j0 + lane];
            int s = src[e];
            int rr = rel[e];
            myIdx = rr * N_NODES + s;
            myC = norm[e] * g_gate[myIdx];
        }
        for (int jj = 0; jj < cnt; jj++) {
            float c  = __shfl_sync(0xffffffffu, myC, jj);
            int idx  = __shfl_sync(0xffffffffu, myIdx, jj);
            float4 v = *((const float4*)g_hrel + (size_t)idx * 32 + lane);
            acc.x += c * v.x; acc.y += c * v.y;
            acc.z += c * v.z; acc.w += c * v.w;
        }
    }
    float4 o = ((float4*)out)[(size_t)w * 32 + lane];
    o.x = fmaxf(o.x + acc.x, 0.f);
    o.y = fmaxf(o.y + acc.y, 0.f);
    o.z = fmaxf(o.z + acc.z, 0.f);
    o.w = fmaxf(o.w + acc.w, 0.f);
    ((float4*)out)[(size_t)w * 32 + lane] = o;
}

// ---------------- launch ---------------------------------------------------
extern "C" void kernel_launch(void* const* d_in, const int* in_sizes, int n_in,
                              void* d_out, int out_size)
{
    const float* h      = (const float*)d_in[0];
    const float* weight = (const float*)d_in[1];
    const float* gate_w = (const float*)d_in[2];
    const float* h_bias = (const float*)d_in[3];
    const float* loop_w = (const float*)d_in[4];
    const float* norm   = (const float*)d_in[5];
    const int*   src    = (const int*)d_in[6];
    const int*   dst    = (const int*)d_in[7];
    const int*   rel    = (const int*)d_in[8];
    float* out = (float*)d_out;

    // CSR build (deterministic work each call)
    zero_cnt_k<<<(N_NODES + 255) / 256, 256>>>();
    count_k<<<(N_EDGES + 255) / 256, 256>>>(dst);
    scan_k<<<1, 1024>>>();
    fill_k<<<(N_EDGES + 255) / 256, 256>>>(dst);

    // gate values
    gate_k<<<N_NODES / 8, 256>>>(h, gate_w);

    // 8 relation GEMMs + self-loop/bias GEMM (writes out)
    cudaFuncSetAttribute(gemm_k, cudaFuncAttributeMaxDynamicSharedMemorySize,
                         SMEM_FLOATS * (int)sizeof(float));
    dim3 grid((N_NODES + 127) / 128, NRELS + 1);
    gemm_k<<<grid, 256, SMEM_FLOATS * sizeof(float)>>>(h, weight, loop_w, h_bias, out);

    // gather-aggregate + ReLU
    agg_k<<<N_NODES / 8, 256>>>(norm, src, rel, out);
}

// round 3
// speedup vs baseline: 1.0654x; 1.0654x over previous
#include <cuda_runtime.h>
#include <cuda_bf16.h>
#include <cstdint>

// Problem constants (fixed shapes per reference)
#define N_NODES 50000
#define N_EDGES 600000
#define NRELS   8
#define F       128

// ---------------- scratch (static device globals; no allocation) ------------
__device__ float g_hrel[(size_t)NRELS * N_NODES * F];   // [R][N][F] ~205 MB
__device__ float g_gate[NRELS * N_NODES];               // sigmoid(gate) [R][N]
__device__ int   g_cnt[N_NODES];
__device__ int   g_off[N_NODES + 1];
__device__ int   g_cursor[N_NODES];
__device__ int   g_eidx[N_EDGES];

// ---------------- CSR build ------------------------------------------------
__global__ void zero_cnt_k() {
    int i = blockIdx.x * blockDim.x + threadIdx.x;
    if (i < N_NODES) g_cnt[i] = 0;
}

__global__ void count_k(const int* __restrict__ dst) {
    int i = blockIdx.x * blockDim.x + threadIdx.x;
    if (i < N_EDGES) atomicAdd(&g_cnt[dst[i]], 1);
}

// single-block exclusive scan over 50000 counts
__global__ void scan_k() {
    __shared__ int wsum[32];
    __shared__ int carry_s;
    int t = threadIdx.x;
    if (t == 0) carry_s = 0;
    __syncthreads();
    for (int base = 0; base < N_NODES; base += 1024) {
        int i = base + t;
        int v = (i < N_NODES) ? g_cnt[i] : 0;
        int x = v;  // inclusive scan within warp
        #pragma unroll
        for (int d = 1; d < 32; d <<= 1) {
            int y = __shfl_up_sync(0xffffffffu, x, d);
            if ((t & 31) >= d) x += y;
        }
        if ((t & 31) == 31) wsum[t >> 5] = x;
        __syncthreads();
        if (t < 32) {
            int y = wsum[t];
            int z = y;
            #pragma unroll
            for (int d = 1; d < 32; d <<= 1) {
                int u = __shfl_up_sync(0xffffffffu, z, d);
                if (t >= d) z += u;
            }
            wsum[t] = z - y;   // exclusive warp offsets
        }
        __syncthreads();
        int excl = x - v + wsum[t >> 5];
        int off = carry_s + excl;
        if (i < N_NODES) { g_off[i] = off; g_cursor[i] = off; }
        __syncthreads();   // everyone has read carry_s
        if (t == 1023) carry_s = off + v;  // inclusive total of this chunk
        __syncthreads();
    }
    if (t == 0) g_off[N_NODES] = carry_s;
}

__global__ void fill_k(const int* __restrict__ dst) {
    int i = blockIdx.x * blockDim.x + threadIdx.x;
    if (i < N_EDGES) {
        int p = atomicAdd(&g_cursor[dst[i]], 1);
        g_eidx[p] = i;
    }
}

// ---------------- gate: sigmoid(h . gate_w[r]) per (r, node) ---------------
__global__ void gate_k(const float* __restrict__ h, const float* __restrict__ gw) {
    int w = (blockIdx.x * blockDim.x + threadIdx.x) >> 5;   // node (warp per node)
    int lane = threadIdx.x & 31;
    if (w >= N_NODES) return;
    float4 hv = ((const float4*)h)[(size_t)w * 32 + lane];
    #pragma unroll
    for (int r = 0; r < NRELS; r++) {
        float4 g4 = ((const float4*)gw)[r * 32 + lane];
        float p = hv.x * g4.x + hv.y * g4.y + hv.z * g4.z + hv.w * g4.w;
        #pragma unroll
        for (int d = 16; d; d >>= 1) p += __shfl_xor_sync(0xffffffffu, p, d);
        if (lane == 0) g_gate[r * N_NODES + w] = 1.0f / (1.0f + __expf(-p));
    }
}

// ---------------- mma.sync bf16 GEMM ---------------------------------------
// Per block: 128 (nodes) x 128 (out) x 128 (K) tile, 256 threads (8 warps).
// fp32 inputs split into bf16 hi/lo; D = Ahi*Bhi + Ahi*Blo + Alo*Bhi (fp32 acc).
// A in smem row-major [m][k], B in smem K-major [n][k]; row stride 136 bf16
// (272 B -> 8 consecutive rows land in distinct 16B banks: conflict-free ldmatrix).
#define ROWS_STRIDE 136                       // bf16 elems per smem row
#define TILE_BYTES  (128 * ROWS_STRIDE * 2)   // 34816 B
#define SM_A_HI 0
#define SM_A_LO (SM_A_HI + TILE_BYTES)
#define SM_B_HI (SM_A_LO + TILE_BYTES)
#define SM_B_LO (SM_B_HI + TILE_BYTES)
#define SM_TOTAL (SM_B_LO + TILE_BYTES)

__device__ __forceinline__ uint32_t smem_u32(const void* p) {
    uint32_t a;
    asm("{ .reg .u64 t; cvta.to.shared.u64 t, %1; cvt.u32.u64 %0, t; }"
        : "=r"(a) : "l"(p));
    return a;
}

__device__ __forceinline__ void ldm_x4(uint32_t* r, uint32_t addr) {
    asm volatile("ldmatrix.sync.aligned.m8n8.x4.shared.b16 {%0,%1,%2,%3}, [%4];"
                 : "=r"(r[0]), "=r"(r[1]), "=r"(r[2]), "=r"(r[3]) : "r"(addr));
}

__device__ __forceinline__ void mma_bf16(float* c, const uint32_t* a,
                                         uint32_t b0, uint32_t b1) {
    asm volatile(
        "mma.sync.aligned.m16n8k16.row.col.f32.bf16.bf16.f32 "
        "{%0,%1,%2,%3}, {%4,%5,%6,%7}, {%8,%9}, {%0,%1,%2,%3};"
        : "+f"(c[0]), "+f"(c[1]), "+f"(c[2]), "+f"(c[3])
        : "r"(a[0]), "r"(a[1]), "r"(a[2]), "r"(a[3]), "r"(b0), "r"(b1));
}

__device__ __forceinline__ uint32_t pack2bf(float a, float b) {
    __nv_bfloat162 t = __floats2bfloat162_rn(a, b);
    return *(uint32_t*)&t;
}

__global__ void __launch_bounds__(256, 1) gemm_tc_k(
    const float* __restrict__ h, const float* __restrict__ weight,
    const float* __restrict__ loopw, const float* __restrict__ bias,
    float* __restrict__ out)
{
    extern __shared__ char smem[];
    uint32_t sbase = smem_u32(smem);
    int tid = threadIdx.x;
    int wid = tid >> 5;
    int lane = tid & 31;
    int r = blockIdx.y;
    int nodeBase = blockIdx.x * 128;
    const float* W = (r < NRELS) ? (weight + (size_t)r * F * F) : loopw;

    // ---- load + split-convert A tile (rows=nodes, cols=K); zero-pad OOR ----
    for (int idx = tid; idx < 128 * 32; idx += 256) {
        int m = idx >> 5;
        int c4 = idx & 31;               // float4 index along K
        int row = nodeBase + m;
        float4 v = (row < N_NODES) ? ((const float4*)h)[(size_t)row * 32 + c4]
                                   : make_float4(0.f, 0.f, 0.f, 0.f);
        float hx = __bfloat162float(__float2bfloat16(v.x));
        float hy = __bfloat162float(__float2bfloat16(v.y));
        float hz = __bfloat162float(__float2bfloat16(v.z));
        float hw = __bfloat162float(__float2bfloat16(v.w));
        uint32_t off = (uint32_t)m * (ROWS_STRIDE * 2) + (uint32_t)c4 * 8;
        uint2 hv; hv.x = pack2bf(hx, hy); hv.y = pack2bf(hz, hw);
        *(uint2*)(smem + SM_A_HI + off) = hv;
        uint2 lv; lv.x = pack2bf(v.x - hx, v.y - hy);
                  lv.y = pack2bf(v.z - hz, v.w - hw);
        *(uint2*)(smem + SM_A_LO + off) = lv;
    }

    // ---- load + split-convert B: W is [k][n] row-major -> Bs[n][k] K-major ----
    for (int idx = tid; idx < 128 * 32; idx += 256) {
        int k = idx >> 5;
        int c4 = idx & 31;
        float4 v = ((const float4*)W)[(size_t)k * 32 + c4];
        float vv[4] = {v.x, v.y, v.z, v.w};
        #pragma unroll
        for (int j = 0; j < 4; j++) {
            int n = c4 * 4 + j;
            float hi = __bfloat162float(__float2bfloat16(vv[j]));
            uint32_t off = (uint32_t)n * (ROWS_STRIDE * 2) + (uint32_t)k * 2;
            *(__nv_bfloat16*)(smem + SM_B_HI + off) = __float2bfloat16(hi);
            *(__nv_bfloat16*)(smem + SM_B_LO + off) = __float2bfloat16(vv[j] - hi);
        }
    }
    __syncthreads();

    // ---- warp tiling: 8 warps in 2(m) x 4(n); warp tile 64m x 32n ----
    int warpM = (wid & 1) * 64;
    int warpN = (wid >> 1) * 32;

    float acc[4][4][4];                 // [m-frag][n-frag][reg]
    #pragma unroll
    for (int i = 0; i < 4; i++)
        #pragma unroll
        for (int j = 0; j < 4; j++)
            #pragma unroll
            for (int q = 0; q < 4; q++) acc[i][j][q] = 0.f;

    // ldmatrix per-lane address components
    int aRow = warpM + (lane & 15);
    int aColOff = (lane >> 4) << 3;           // 0 or 8
    int bRow = warpN + (lane & 7) + ((lane >> 4) << 3);
    int bColOff = lane & 8;                    // 0 or 8

    #pragma unroll
    for (int p = 0; p < 3; p++) {
        uint32_t aBase = sbase + ((p == 2) ? SM_A_LO : SM_A_HI);
        uint32_t bBase = sbase + ((p == 1) ? SM_B_LO : SM_B_HI);
        #pragma unroll
        for (int ks = 0; ks < 8; ks++) {
            int k0 = ks * 16;
            uint32_t afr[4][4];
            #pragma unroll
            for (int mf = 0; mf < 4; mf++) {
                uint32_t addr = aBase + (uint32_t)(aRow + mf * 16) * (ROWS_STRIDE * 2)
                              + (uint32_t)(k0 + aColOff) * 2;
                ldm_x4(afr[mf], addr);
            }
            uint32_t bfr[2][4];
            #pragma unroll
            for (int nf2 = 0; nf2 < 2; nf2++) {
                uint32_t addr = bBase + (uint32_t)(bRow + nf2 * 16) * (ROWS_STRIDE * 2)
                              + (uint32_t)(k0 + bColOff) * 2;
                ldm_x4(bfr[nf2], addr);
            }
            #pragma unroll
            for (int mf = 0; mf < 4; mf++)
                #pragma unroll
                for (int nf = 0; nf < 4; nf++)
                    mma_bf16(acc[mf][nf], afr[mf],
                             bfr[nf >> 1][(nf & 1) * 2],
                             bfr[nf >> 1][(nf & 1) * 2 + 1]);
        }
    }

    // ---- epilogue: write fp32 accumulators ----
    int lr = lane >> 2;                  // row within 8
    int lc = (lane & 3) << 1;            // col within 8
    #pragma unroll
    for (int mf = 0; mf < 4; mf++) {
        int row0 = nodeBase + warpM + mf * 16 + lr;
        int row1 = row0 + 8;
        #pragma unroll
        for (int nf = 0; nf < 4; nf++) {
            int col = warpN + nf * 8 + lc;
            if (r < NRELS) {
                if (row0 < N_NODES)
                    *(float2*)(g_hrel + ((size_t)r * N_NODES + row0) * F + col)
                        = make_float2(acc[mf][nf][0], acc[mf][nf][1]);
                if (row1 < N_NODES)
                    *(float2*)(g_hrel + ((size_t)r * N_NODES + row1) * F + col)
                        = make_float2(acc[mf][nf][2], acc[mf][nf][3]);
            } else {
                float b0 = bias[col], b1 = bias[col + 1];
                if (row0 < N_NODES)
                    *(float2*)(out + (size_t)row0 * F + col)
                        = make_float2(acc[mf][nf][0] + b0, acc[mf][nf][1] + b1);
                if (row1 < N_NODES)
                    *(float2*)(out + (size_t)row1 * F + col)
                        = make_float2(acc[mf][nf][2] + b0, acc[mf][nf][3] + b1);
            }
        }
    }
}

// ---------------- aggregate: warp per dst node, CSR gather, fused ReLU -----
__global__ void __launch_bounds__(256) agg_k(
    const float* __restrict__ norm, const int* __restrict__ src,
    const int* __restrict__ rel, float* __restrict__ out)
{
    int w = (blockIdx.x * 256 + threadIdx.x) >> 5;   // node
    int lane = threadIdx.x & 31;
    int beg = g_off[w], end = g_off[w + 1];
    float4 acc = make_float4(0.f, 0.f, 0.f, 0.f);
    for (int j0 = beg; j0 < end; j0 += 32) {
        int cnt = min(32, end - j0);
        int myIdx = 0; float myC = 0.f;
        if (lane < cnt) {
            int e = g_eidx[j0 + lane];
            int s = src[e];
            int rr = rel[e];
            myIdx = rr * N_NODES + s;
            myC = norm[e] * g_gate[myIdx];
        }
        for (int jj = 0; jj < cnt; jj++) {
            float c  = __shfl_sync(0xffffffffu, myC, jj);
            int idx  = __shfl_sync(0xffffffffu, myIdx, jj);
            float4 v = *((const float4*)g_hrel + (size_t)idx * 32 + lane);
            acc.x += c * v.x; acc.y += c * v.y;
            acc.z += c * v.z; acc.w += c * v.w;
        }
    }
    float4 o = ((float4*)out)[(size_t)w * 32 + lane];
    o.x = fmaxf(o.x + acc.x, 0.f);
    o.y = fmaxf(o.y + acc.y, 0.f);
    o.z = fmaxf(o.z + acc.z, 0.f);
    o.w = fmaxf(o.w + acc.w, 0.f);
    ((float4*)out)[(size_t)w * 32 + lane] = o;
}

// ---------------- launch ---------------------------------------------------
extern "C" void kernel_launch(void* const* d_in, const int* in_sizes, int n_in,
                              void* d_out, int out_size)
{
    const float* h      = (const float*)d_in[0];
    const float* weight = (const float*)d_in[1];
    const float* gate_w = (const float*)d_in[2];
    const float* h_bias = (const float*)d_in[3];
    const float* loop_w = (const float*)d_in[4];
    const float* norm   = (const float*)d_in[5];
    const int*   src    = (const int*)d_in[6];
    const int*   dst    = (const int*)d_in[7];
    const int*   rel    = (const int*)d_in[8];
    float* out = (float*)d_out;

    // CSR build (deterministic work each call)
    zero_cnt_k<<<(N_NODES + 255) / 256, 256>>>();
    count_k<<<(N_EDGES + 255) / 256, 256>>>(dst);
    scan_k<<<1, 1024>>>();
    fill_k<<<(N_EDGES + 255) / 256, 256>>>(dst);

    // gate values
    gate_k<<<N_NODES / 8, 256>>>(h, gate_w);

    // 8 relation GEMMs + self-loop/bias GEMM (writes out) — mma.sync bf16 split
    cudaFuncSetAttribute(gemm_tc_k, cudaFuncAttributeMaxDynamicSharedMemorySize,
                         SM_TOTAL);
    dim3 grid((N_NODES + 127) / 128, NRELS + 1);
    gemm_tc_k<<<grid, 256, SM_TOTAL>>>(h, weight, loop_w, h_bias, out);

    // gather-aggregate + ReLU
    agg_k<<<N_NODES / 8, 256>>>(norm, src, rel, out);
}

// round 4
// speedup vs baseline: 1.8611x; 1.7469x over previous
#include <cuda_runtime.h>
#include <cuda_bf16.h>
#include <cstdint>

// Problem constants (fixed shapes per reference)
#define N_NODES 50000
#define N_PAD   50048          // 391 * 128, padded for GEMM tiles
#define N_EDGES 600000
#define NRELS   8
#define F       128
#define KTOT    1152           // 8*128 (relations) + 128 (self-loop)

// ---------------- scratch (static device globals; no allocation) ------------
__device__ __nv_bfloat16 g_ahi[(size_t)N_PAD * KTOT];   // A hi, [N_PAD][1152]
__device__ __nv_bfloat16 g_alo[(size_t)N_PAD * KTOT];   // A lo
__device__ __nv_bfloat16 g_bht[(size_t)F * KTOT];       // B^T hi, [128][1152]
__device__ __nv_bfloat16 g_blt[(size_t)F * KTOT];       // B^T lo
__device__ float g_gate[NRELS * N_NODES];               // sigmoid gate [R][N]
__device__ int   g_cnt[N_NODES];
__device__ int   g_off[N_NODES + 1];
__device__ int   g_cursor[N_NODES];
__device__ int   g_eidx[N_EDGES];

// ---------------- CSR build ------------------------------------------------
__global__ void zero_cnt_k() {
    int i = blockIdx.x * blockDim.x + threadIdx.x;
    if (i < N_NODES) g_cnt[i] = 0;
}

__global__ void count_k(const int* __restrict__ dst) {
    int i = blockIdx.x * blockDim.x + threadIdx.x;
    if (i < N_EDGES) atomicAdd(&g_cnt[dst[i]], 1);
}

// single-block exclusive scan over 50000 counts
__global__ void scan_k() {
    __shared__ int wsum[32];
    __shared__ int carry_s;
    int t = threadIdx.x;
    if (t == 0) carry_s = 0;
    __syncthreads();
    for (int base = 0; base < N_NODES; base += 1024) {
        int i = base + t;
        int v = (i < N_NODES) ? g_cnt[i] : 0;
        int x = v;
        #pragma unroll
        for (int d = 1; d < 32; d <<= 1) {
            int y = __shfl_up_sync(0xffffffffu, x, d);
            if ((t & 31) >= d) x += y;
        }
        if ((t & 31) == 31) wsum[t >> 5] = x;
        __syncthreads();
        if (t < 32) {
            int y = wsum[t];
            int z = y;
            #pragma unroll
            for (int d = 1; d < 32; d <<= 1) {
                int u = __shfl_up_sync(0xffffffffu, z, d);
                if (t >= d) z += u;
            }
            wsum[t] = z - y;
        }
        __syncthreads();
        int excl = x - v + wsum[t >> 5];
        int off = carry_s + excl;
        if (i < N_NODES) { g_off[i] = off; g_cursor[i] = off; }
        __syncthreads();
        if (t == 1023) carry_s = off + v;
        __syncthreads();
    }
    if (t == 0) g_off[N_NODES] = carry_s;
}

__global__ void fill_k(const int* __restrict__ dst) {
    int i = blockIdx.x * blockDim.x + threadIdx.x;
    if (i < N_EDGES) {
        int p = atomicAdd(&g_cursor[dst[i]], 1);
        g_eidx[p] = i;
    }
}

// ---------------- gate: sigmoid(h . gate_w[r]) per (r, node) ---------------
__global__ void gate_k(const float* __restrict__ h, const float* __restrict__ gw) {
    int w = (blockIdx.x * blockDim.x + threadIdx.x) >> 5;
    int lane = threadIdx.x & 31;
    if (w >= N_NODES) return;
    float4 hv = ((const float4*)h)[(size_t)w * 32 + lane];
    #pragma unroll
    for (int r = 0; r < NRELS; r++) {
        float4 g4 = ((const float4*)gw)[r * 32 + lane];
        float p = hv.x * g4.x + hv.y * g4.y + hv.z * g4.z + hv.w * g4.w;
        #pragma unroll
        for (int d = 16; d; d >>= 1) p += __shfl_xor_sync(0xffffffffu, p, d);
        if (lane == 0) g_gate[r * N_NODES + w] = 1.0f / (1.0f + __expf(-p));
    }
}

// ---------------- aggregate-first: build virtual A rows as bf16 hi/lo ------
__device__ __forceinline__ uint32_t pack2bf(float a, float b) {
    __nv_bfloat162 t = __floats2bfloat162_rn(a, b);
    return *(uint32_t*)&t;
}

__device__ __forceinline__ void split_write(__nv_bfloat16* hi_p, __nv_bfloat16* lo_p,
                                            float4 v) {
    float hx = __bfloat162float(__float2bfloat16(v.x));
    float hy = __bfloat162float(__float2bfloat16(v.y));
    float hz = __bfloat162float(__float2bfloat16(v.z));
    float hw = __bfloat162float(__float2bfloat16(v.w));
    uint2 hv; hv.x = pack2bf(hx, hy); hv.y = pack2bf(hz, hw);
    *(uint2*)hi_p = hv;
    uint2 lv; lv.x = pack2bf(v.x - hx, v.y - hy);
              lv.y = pack2bf(v.z - hz, v.w - hw);
    *(uint2*)lo_p = lv;
}

__global__ void __launch_bounds__(256) aggA_k(
    const float* __restrict__ h, const float* __restrict__ norm,
    const int* __restrict__ src, const int* __restrict__ rel)
{
    int w = (blockIdx.x * 256 + threadIdx.x) >> 5;   // node d (0..N_PAD-1)
    int lane = threadIdx.x & 31;
    if (w >= N_PAD) return;

    float4 acc[NRELS];
    #pragma unroll
    for (int q = 0; q < NRELS; q++) acc[q] = make_float4(0.f, 0.f, 0.f, 0.f);

    if (w < N_NODES) {
        int beg = g_off[w], end = g_off[w + 1];
        for (int j0 = beg; j0 < end; j0 += 32) {
            int cnt = min(32, end - j0);
            int pk = 0; float c = 0.f;
            if (lane < cnt) {
                int e = g_eidx[j0 + lane];
                int s = src[e];
                int rr = rel[e];
                pk = s | (rr << 16);               // N_NODES < 2^16
                c = norm[e] * g_gate[rr * N_NODES + s];
            }
            for (int jj = 0; jj < cnt; jj++) {
                float cc = __shfl_sync(0xffffffffu, c, jj);
                int p    = __shfl_sync(0xffffffffu, pk, jj);
                int ss = p & 0xffff;
                int rr = p >> 16;
                float4 v = ((const float4*)h)[(size_t)ss * 32 + lane];
                #pragma unroll
                for (int q = 0; q < NRELS; q++) {
                    if (rr == q) {
                        acc[q].x += cc * v.x; acc[q].y += cc * v.y;
                        acc[q].z += cc * v.z; acc[q].w += cc * v.w;
                    }
                }
            }
        }
    }

    size_t base = (size_t)w * KTOT;
    #pragma unroll
    for (int q = 0; q < NRELS; q++)
        split_write(g_ahi + base + q * F + lane * 4,
                    g_alo + base + q * F + lane * 4, acc[q]);

    float4 hv = (w < N_NODES) ? ((const float4*)h)[(size_t)w * 32 + lane]
                              : make_float4(0.f, 0.f, 0.f, 0.f);
    split_write(g_ahi + base + NRELS * F + lane * 4,
                g_alo + base + NRELS * F + lane * 4, hv);
}

// ---------------- B^T build: [k][n] fp32 -> [n][k] bf16 hi/lo ---------------
__global__ void convB_k(const float* __restrict__ weight,
                        const float* __restrict__ loopw)
{
    int gid = blockIdx.x * blockDim.x + threadIdx.x;   // n*KTOT + k
    if (gid >= F * KTOT) return;
    int n = gid / KTOT;
    int k = gid % KTOT;
    float v = (k < NRELS * F) ? weight[(size_t)k * F + n]
                              : loopw[(size_t)(k - NRELS * F) * F + n];
    float hi = __bfloat162float(__float2bfloat16(v));
    g_bht[gid] = __float2bfloat16(hi);
    g_blt[gid] = __float2bfloat16(v - hi);
}

// ---------------- fused GEMM: out = relu(A_virt @ B + bias) ----------------
// Block: 128 rows x 128 cols, K=1152 in chunks of 32, cp.async 2-stage.
// Smem per matrix chunk: [128 rows][40 bf16] (80 B stride, 16B-aligned,
// conflict-free for ldmatrix). 4 matrices (Ahi,Alo,Bhi,Blo) x 2 stages.
#define KCH 32
#define NCHUNKS (KTOT / KCH)      // 36
#define RSTRIDE_B 80              // bytes per smem row
#define MAT_BYTES (128 * RSTRIDE_B)     // 10240
#define STAGE_BYTES (4 * MAT_BYTES)     // 40960
#define GEMM_SMEM (2 * STAGE_BYTES)     // 81920

__device__ __forceinline__ uint32_t smem_u32(const void* p) {
    uint32_t a;
    asm("{ .reg .u64 t; cvta.to.shared.u64 t, %1; cvt.u32.u64 %0, t; }"
        : "=r"(a) : "l"(p));
    return a;
}

__device__ __forceinline__ void cp16(uint32_t dst, const void* src) {
    asm volatile("cp.async.ca.shared.global [%0], [%1], 16;"
                 :: "r"(dst), "l"(src));
}
__device__ __forceinline__ void cp_commit() {
    asm volatile("cp.async.commit_group;");
}
template <int N> __device__ __forceinline__ void cp_wait() {
    asm volatile("cp.async.wait_group %0;" :: "n"(N));
}

__device__ __forceinline__ void ldm_x4(uint32_t* r, uint32_t addr) {
    asm volatile("ldmatrix.sync.aligned.m8n8.x4.shared.b16 {%0,%1,%2,%3}, [%4];"
                 : "=r"(r[0]), "=r"(r[1]), "=r"(r[2]), "=r"(r[3]) : "r"(addr));
}

__device__ __forceinline__ void mma_bf16(float* c, const uint32_t* a,
                                         uint32_t b0, uint32_t b1) {
    asm volatile(
        "mma.sync.aligned.m16n8k16.row.col.f32.bf16.bf16.f32 "
        "{%0,%1,%2,%3}, {%4,%5,%6,%7}, {%8,%9}, {%0,%1,%2,%3};"
        : "+f"(c[0]), "+f"(c[1]), "+f"(c[2]), "+f"(c[3])
        : "r"(a[0]), "r"(a[1]), "r"(a[2]), "r"(a[3]), "r"(b0), "r"(b1));
}

__global__ void __launch_bounds__(256, 2) gemm_k(
    const float* __restrict__ bias, float* __restrict__ out)
{
    extern __shared__ char smem[];
    uint32_t sbase = smem_u32(smem);
    int tid = threadIdx.x;
    int wid = tid >> 5;
    int lane = tid & 31;
    int nodeBase = blockIdx.x * 128;

    // chunk loader: 2048 cp.async.16 per chunk, 8 per thread
    auto load_chunk = [&](int stg, int kc) {
        #pragma unroll
        for (int part = 0; part < 8; part++) {
            int idx = part * 256 + tid;          // 0..2047
            int mat = idx >> 9;                  // 0:Ahi 1:Alo 2:Bhi 3:Blo
            int t2 = idx & 511;
            int row = t2 >> 2;
            int seg = t2 & 3;
            uint32_t dst = sbase + stg * STAGE_BYTES + mat * MAT_BYTES
                         + row * RSTRIDE_B + seg * 16;
            const __nv_bfloat16* sp;
            if (mat == 0)      sp = g_ahi + (size_t)(nodeBase + row) * KTOT + kc + seg * 8;
            else if (mat == 1) sp = g_alo + (size_t)(nodeBase + row) * KTOT + kc + seg * 8;
            else if (mat == 2) sp = g_bht + (size_t)row * KTOT + kc + seg * 8;
            else               sp = g_blt + (size_t)row * KTOT + kc + seg * 8;
            cp16(dst, sp);
        }
    };

    // warp tiling: 8 warps in 2(m) x 4(n); warp tile 64m x 32n
    int warpM = (wid & 1) * 64;
    int warpN = (wid >> 1) * 32;

    float acc[4][4][4];
    #pragma unroll
    for (int i = 0; i < 4; i++)
        #pragma unroll
        for (int j = 0; j < 4; j++)
            #pragma unroll
            for (int q = 0; q < 4; q++) acc[i][j][q] = 0.f;

    int aRow = warpM + (lane & 15);
    int aColOff = (lane >> 4) << 3;
    int bRow = warpN + (lane & 7) + ((lane >> 4) << 3);
    int bColOff = lane & 8;

    load_chunk(0, 0);
    cp_commit();

    for (int c = 0; c < NCHUNKS; c++) {
        if (c + 1 < NCHUNKS) {
            load_chunk((c + 1) & 1, (c + 1) * KCH);
            cp_commit();
            cp_wait<1>();
        } else {
            cp_wait<0>();
        }
        __syncthreads();

        uint32_t stgBase = sbase + (c & 1) * STAGE_BYTES;
        #pragma unroll
        for (int p = 0; p < 3; p++) {
            uint32_t aB = stgBase + ((p == 2) ? MAT_BYTES : 0);
            uint32_t bB = stgBase + 2 * MAT_BYTES + ((p == 1) ? MAT_BYTES : 0);
            #pragma unroll
            for (int ks = 0; ks < 2; ks++) {
                int k0 = ks * 16;
                uint32_t afr[4][4];
                #pragma unroll
                for (int mf = 0; mf < 4; mf++)
                    ldm_x4(afr[mf], aB + (uint32_t)(aRow + mf * 16) * RSTRIDE_B
                                       + (uint32_t)(k0 + aColOff) * 2);
                uint32_t bfr[2][4];
                #pragma unroll
                for (int nf2 = 0; nf2 < 2; nf2++)
                    ldm_x4(bfr[nf2], bB + (uint32_t)(bRow + nf2 * 16) * RSTRIDE_B
                                        + (uint32_t)(k0 + bColOff) * 2);
                #pragma unroll
                for (int mf = 0; mf < 4; mf++)
                    #pragma unroll
                    for (int nf = 0; nf < 4; nf++)
                        mma_bf16(acc[mf][nf], afr[mf],
                                 bfr[nf >> 1][(nf & 1) * 2],
                                 bfr[nf >> 1][(nf & 1) * 2 + 1]);
            }
        }
        __syncthreads();
    }

    // epilogue: +bias, ReLU, store
    int lr = lane >> 2;
    int lc = (lane & 3) << 1;
    #pragma unroll
    for (int mf = 0; mf < 4; mf++) {
        int row0 = nodeBase + warpM + mf * 16 + lr;
        int row1 = row0 + 8;
        #pragma unroll
        for (int nf = 0; nf < 4; nf++) {
            int col = warpN + nf * 8 + lc;
            float b0 = bias[col], b1 = bias[col + 1];
            if (row0 < N_NODES)
                *(float2*)(out + (size_t)row0 * F + col)
                    = make_float2(fmaxf(acc[mf][nf][0] + b0, 0.f),
                                  fmaxf(acc[mf][nf][1] + b1, 0.f));
            if (row1 < N_NODES)
                *(float2*)(out + (size_t)row1 * F + col)
                    = make_float2(fmaxf(acc[mf][nf][2] + b0, 0.f),
                                  fmaxf(acc[mf][nf][3] + b1, 0.f));
        }
    }
}

// ---------------- launch ---------------------------------------------------
extern "C" void kernel_launch(void* const* d_in, const int* in_sizes, int n_in,
                              void* d_out, int out_size)
{
    const float* h      = (const float*)d_in[0];
    const float* weight = (const float*)d_in[1];
    const float* gate_w = (const float*)d_in[2];
    const float* h_bias = (const float*)d_in[3];
    const float* loop_w = (const float*)d_in[4];
    const float* norm   = (const float*)d_in[5];
    const int*   src    = (const int*)d_in[6];
    const int*   dst    = (const int*)d_in[7];
    const int*   rel    = (const int*)d_in[8];
    float* out = (float*)d_out;

    // CSR build over dst
    zero_cnt_k<<<(N_NODES + 255) / 256, 256>>>();
    count_k<<<(N_EDGES + 255) / 256, 256>>>(dst);
    scan_k<<<1, 1024>>>();
    fill_k<<<(N_EDGES + 255) / 256, 256>>>(dst);

    // gate values
    gate_k<<<N_NODES / 8, 256>>>(h, gate_w);

    // aggregate-first: build virtual A rows (bf16 hi/lo), incl. h block + padding
    aggA_k<<<N_PAD / 8, 256>>>(h, norm, src, rel);

    // B^T hi/lo
    convB_k<<<(F * KTOT + 255) / 256, 256>>>(weight, loop_w);

    // fused GEMM + bias + ReLU
    cudaFuncSetAttribute(gemm_k, cudaFuncAttributeMaxDynamicSharedMemorySize,
                         GEMM_SMEM);
    gemm_k<<<N_PAD / 128, 256, GEMM_SMEM>>>(h_bias, out);
}

// round 5
// speedup vs baseline: 3.5306x; 1.8970x over previous
#include <cuda_runtime.h>
#include <cuda_bf16.h>
#include <cuda_fp16.h>
#include <cstdint>

// Problem constants (fixed shapes per reference)
#define N_NODES 50000
#define N_PAD   50048          // 391 * 128, padded for GEMM tiles
#define N_EDGES 600000
#define NRELS   8
#define F       128
#define KTOT    1152           // 8*128 (relations) + 128 (self-loop)

#define SCAN_BLK 512
#define SCAN_NB  ((N_NODES + SCAN_BLK - 1) / SCAN_BLK)   // 98

// ---------------- scratch (static device globals; no allocation) ------------
__device__ __half g_af16[(size_t)N_PAD * KTOT];   // virtual A, fp16 [N_PAD][1152]
__device__ __half g_bf16[(size_t)F * KTOT];       // B^T fp16 [128][1152]
__device__ float g_gate[NRELS * N_NODES];         // sigmoid gate [R][N]
__device__ int   g_cnt[N_NODES];                  // zero-init; re-zeroed each call
__device__ int   g_off[N_NODES + 1];
__device__ int   g_cursor[N_NODES];
__device__ int   g_eidx[N_EDGES];
__device__ int   g_bsum[SCAN_NB];
__device__ int   g_boff[SCAN_NB];

// ---------------- CSR build ------------------------------------------------
__global__ void count_k(const int* __restrict__ dst) {
    int i = blockIdx.x * blockDim.x + threadIdx.x;
    if (i < N_EDGES) atomicAdd(&g_cnt[dst[i]], 1);
}

// phase 1: per-block sums of counts
__global__ void scan1_k() {
    __shared__ int ws[16];
    int b = blockIdx.x, t = threadIdx.x;
    int i = b * SCAN_BLK + t;
    int v = (i < N_NODES) ? g_cnt[i] : 0;
    #pragma unroll
    for (int d = 16; d; d >>= 1) v += __shfl_xor_sync(0xffffffffu, v, d);
    if ((t & 31) == 0) ws[t >> 5] = v;
    __syncthreads();
    if (t == 0) {
        int s = 0;
        #pragma unroll
        for (int j = 0; j < 16; j++) s += ws[j];
        g_bsum[b] = s;
    }
}

// phase 2: exclusive scan of 98 block sums (1 block, 128 threads)
__global__ void scan2_k() {
    __shared__ int ws[4];
    int t = threadIdx.x;
    int v = (t < SCAN_NB) ? g_bsum[t] : 0;
    int x = v;
    #pragma unroll
    for (int d = 1; d < 32; d <<= 1) {
        int y = __shfl_up_sync(0xffffffffu, x, d);
        if ((t & 31) >= d) x += y;
    }
    if ((t & 31) == 31) ws[t >> 5] = x;
    __syncthreads();
    if (t == 0) {
        int run = 0;
        #pragma unroll
        for (int j = 0; j < 4; j++) { int tmp = ws[j]; ws[j] = run; run += tmp; }
        g_off[N_NODES] = run;
    }
    __syncthreads();
    int excl = x - v + ws[t >> 5];
    if (t < SCAN_NB) g_boff[t] = excl;
}

// phase 3: per-block exclusive rescan + block offset -> g_off, g_cursor
__global__ void scan3_k() {
    __shared__ int ws[16];
    int b = blockIdx.x, t = threadIdx.x;
    int i = b * SCAN_BLK + t;
    int v = (i < N_NODES) ? g_cnt[i] : 0;
    int x = v;
    #pragma unroll
    for (int d = 1; d < 32; d <<= 1) {
        int y = __shfl_up_sync(0xffffffffu, x, d);
        if ((t & 31) >= d) x += y;
    }
    if ((t & 31) == 31) ws[t >> 5] = x;
    __syncthreads();
    if (t == 0) {
        int run = 0;
        #pragma unroll
        for (int j = 0; j < 16; j++) { int tmp = ws[j]; ws[j] = run; run += tmp; }
    }
    __syncthreads();
    int excl = x - v + ws[t >> 5] + g_boff[b];
    if (i < N_NODES) { g_off[i] = excl; g_cursor[i] = excl; }
}

__global__ void fill_k(const int* __restrict__ dst) {
    int i = blockIdx.x * blockDim.x + threadIdx.x;
    if (i < N_EDGES) {
        int p = atomicAdd(&g_cursor[dst[i]], 1);
        g_eidx[p] = i;
    }
    if (i < N_NODES) g_cnt[i] = 0;   // restore zeros for next call
}

// ---------------- gate: sigmoid(h . gate_w[r]) per (r, node) ---------------
__global__ void gate_k(const float* __restrict__ h, const float* __restrict__ gw) {
    int w = (blockIdx.x * blockDim.x + threadIdx.x) >> 5;
    int lane = threadIdx.x & 31;
    if (w >= N_NODES) return;
    float4 hv = ((const float4*)h)[(size_t)w * 32 + lane];
    #pragma unroll
    for (int r = 0; r < NRELS; r++) {
        float4 g4 = ((const float4*)gw)[r * 32 + lane];
        float p = hv.x * g4.x + hv.y * g4.y + hv.z * g4.z + hv.w * g4.w;
        #pragma unroll
        for (int d = 16; d; d >>= 1) p += __shfl_xor_sync(0xffffffffu, p, d);
        if (lane == 0) g_gate[r * N_NODES + w] = 1.0f / (1.0f + __expf(-p));
    }
}

// ---------------- aggregate-first: build virtual A rows (fp16) -------------
__device__ __forceinline__ uint32_t pack2h(float a, float b) {
    __half2 t = __floats2half2_rn(a, b);
    return *(uint32_t*)&t;
}

__device__ __forceinline__ void h16_write(__half* p, float4 v) {
    uint2 o; o.x = pack2h(v.x, v.y); o.y = pack2h(v.z, v.w);
    *(uint2*)p = o;
}

__global__ void __launch_bounds__(256) aggA_k(
    const float* __restrict__ h, const float* __restrict__ norm,
    const int* __restrict__ src, const int* __restrict__ rel)
{
    int w = (blockIdx.x * 256 + threadIdx.x) >> 5;   // node d (0..N_PAD-1)
    int lane = threadIdx.x & 31;
    if (w >= N_PAD) return;

    float4 acc[NRELS];
    #pragma unroll
    for (int q = 0; q < NRELS; q++) acc[q] = make_float4(0.f, 0.f, 0.f, 0.f);

    if (w < N_NODES) {
        int beg = g_off[w], end = g_off[w + 1];
        for (int j0 = beg; j0 < end; j0 += 32) {
            int cnt = min(32, end - j0);
            int pk = 0; float c = 0.f;
            if (lane < cnt) {
                int e = g_eidx[j0 + lane];
                int s = src[e];
                int rr = rel[e];
                pk = s | (rr << 16);               // N_NODES < 2^16
                c = norm[e] * g_gate[rr * N_NODES + s];
            }
            for (int jj = 0; jj < cnt; jj++) {
                float cc = __shfl_sync(0xffffffffu, c, jj);
                int p    = __shfl_sync(0xffffffffu, pk, jj);
                int ss = p & 0xffff;
                int rr = p >> 16;                  // warp-uniform
                float4 v = ((const float4*)h)[(size_t)ss * 32 + lane];
                #define AGG_CASE(q) case q: \
                    acc[q].x += cc * v.x; acc[q].y += cc * v.y; \
                    acc[q].z += cc * v.z; acc[q].w += cc * v.w; break;
                switch (rr) {
                    AGG_CASE(0) AGG_CASE(1) AGG_CASE(2) AGG_CASE(3)
                    AGG_CASE(4) AGG_CASE(5) AGG_CASE(6) AGG_CASE(7)
                }
                #undef AGG_CASE
            }
        }
    }

    size_t base = (size_t)w * KTOT;
    #pragma unroll
    for (int q = 0; q < NRELS; q++)
        h16_write(g_af16 + base + q * F + lane * 4, acc[q]);

    float4 hv = (w < N_NODES) ? ((const float4*)h)[(size_t)w * 32 + lane]
                              : make_float4(0.f, 0.f, 0.f, 0.f);
    h16_write(g_af16 + base + NRELS * F + lane * 4, hv);
}

// ---------------- B^T build: [k][n] fp32 -> [n][k] fp16 --------------------
__global__ void convB_k(const float* __restrict__ weight,
                        const float* __restrict__ loopw)
{
    int gid = blockIdx.x * blockDim.x + threadIdx.x;   // n*KTOT + k
    if (gid >= F * KTOT) return;
    int n = gid / KTOT;
    int k = gid % KTOT;
    float v = (k < NRELS * F) ? weight[(size_t)k * F + n]
                              : loopw[(size_t)(k - NRELS * F) * F + n];
    g_bf16[gid] = __float2half_rn(v);
}

// ---------------- fused GEMM: out = relu(A @ B + bias), single-pass fp16 ---
// Block: 128 rows x 128 cols, K=1152 in chunks of 32, cp.async 3-stage.
#define KCH 32
#define NCHUNKS (KTOT / KCH)            // 36
#define RSTRIDE_B 80                    // bytes per smem row (40 halves)
#define MAT_BYTES (128 * RSTRIDE_B)     // 10240
#define STAGE_BYTES (2 * MAT_BYTES)     // 20480 (A + B)
#define NSTAGE 3
#define GEMM_SMEM (NSTAGE * STAGE_BYTES) // 61440

__device__ __forceinline__ uint32_t smem_u32(const void* p) {
    uint32_t a;
    asm("{ .reg .u64 t; cvta.to.shared.u64 t, %1; cvt.u32.u64 %0, t; }"
        : "=r"(a) : "l"(p));
    return a;
}

__device__ __forceinline__ void cp16(uint32_t dst, const void* src) {
    asm volatile("cp.async.ca.shared.global [%0], [%1], 16;"
                 :: "r"(dst), "l"(src));
}
__device__ __forceinline__ void cp_commit() {
    asm volatile("cp.async.commit_group;");
}
template <int N> __device__ __forceinline__ void cp_wait() {
    asm volatile("cp.async.wait_group %0;" :: "n"(N));
}

__device__ __forceinline__ void ldm_x4(uint32_t* r, uint32_t addr) {
    asm volatile("ldmatrix.sync.aligned.m8n8.x4.shared.b16 {%0,%1,%2,%3}, [%4];"
                 : "=r"(r[0]), "=r"(r[1]), "=r"(r[2]), "=r"(r[3]) : "r"(addr));
}

__device__ __forceinline__ void mma_f16(float* c, const uint32_t* a,
                                        uint32_t b0, uint32_t b1) {
    asm volatile(
        "mma.sync.aligned.m16n8k16.row.col.f32.f16.f16.f32 "
        "{%0,%1,%2,%3}, {%4,%5,%6,%7}, {%8,%9}, {%0,%1,%2,%3};"
        : "+f"(c[0]), "+f"(c[1]), "+f"(c[2]), "+f"(c[3])
        : "r"(a[0]), "r"(a[1]), "r"(a[2]), "r"(a[3]), "r"(b0), "r"(b1));
}

__global__ void __launch_bounds__(256, 2) gemm_k(
    const float* __restrict__ bias, float* __restrict__ out)
{
    extern __shared__ char smem[];
    uint32_t sbase = smem_u32(smem);
    int tid = threadIdx.x;
    int wid = tid >> 5;
    int lane = tid & 31;
    int nodeBase = blockIdx.x * 128;

    // chunk loader: 1024 cp.async.16 per chunk, 4 per thread
    auto load_chunk = [&](int stg, int kc) {
        #pragma unroll
        for (int part = 0; part < 4; part++) {
            int idx = part * 256 + tid;          // 0..1023
            int mat = idx >> 9;                  // 0:A 1:B
            int t2 = idx & 511;
            int row = t2 >> 2;
            int seg = t2 & 3;
            uint32_t dst = sbase + stg * STAGE_BYTES + mat * MAT_BYTES
                         + row * RSTRIDE_B + seg * 16;
            const __half* sp = mat
                ? (g_bf16 + (size_t)row * KTOT + kc + seg * 8)
                : (g_af16 + (size_t)(nodeBase + row) * KTOT + kc + seg * 8);
            cp16(dst, sp);
        }
    };

    // warp tiling: 8 warps in 2(m) x 4(n); warp tile 64m x 32n
    int warpM = (wid & 1) * 64;
    int warpN = (wid >> 1) * 32;

    float acc[4][4][4];
    #pragma unroll
    for (int i = 0; i < 4; i++)
        #pragma unroll
        for (int j = 0; j < 4; j++)
            #pragma unroll
            for (int q = 0; q < 4; q++) acc[i][j][q] = 0.f;

    int aRow = warpM + (lane & 15);
    int aColOff = (lane >> 4) << 3;
    int bRow = warpN + (lane & 7) + ((lane >> 4) << 3);
    int bColOff = lane & 8;

    load_chunk(0, 0);
    cp_commit();
    load_chunk(1, KCH);
    cp_commit();

    for (int c = 0; c < NCHUNKS; c++) {
        if (c == NCHUNKS - 1) cp_wait<0>(); else cp_wait<1>();
        __syncthreads();
        if (c + 2 < NCHUNKS) {
            load_chunk((c + 2) % NSTAGE, (c + 2) * KCH);
            cp_commit();
        }

        uint32_t stgBase = sbase + (c % NSTAGE) * STAGE_BYTES;
        uint32_t aB = stgBase;
        uint32_t bB = stgBase + MAT_BYTES;
        #pragma unroll
        for (int ks = 0; ks < 2; ks++) {
            int k0 = ks * 16;
            uint32_t afr[4][4];
            #pragma unroll
            for (int mf = 0; mf < 4; mf++)
                ldm_x4(afr[mf], aB + (uint32_t)(aRow + mf * 16) * RSTRIDE_B
                                   + (uint32_t)(k0 + aColOff) * 2);
            uint32_t bfr[2][4];
            #pragma unroll
            for (int nf2 = 0; nf2 < 2; nf2++)
                ldm_x4(bfr[nf2], bB + (uint32_t)(bRow + nf2 * 16) * RSTRIDE_B
                                    + (uint32_t)(k0 + bColOff) * 2);
            #pragma unroll
            for (int mf = 0; mf < 4; mf++)
                #pragma unroll
                for (int nf = 0; nf < 4; nf++)
                    mma_f16(acc[mf][nf], afr[mf],
                            bfr[nf >> 1][(nf & 1) * 2],
                            bfr[nf >> 1][(nf & 1) * 2 + 1]);
        }
        __syncthreads();
    }

    // epilogue: +bias, ReLU, store
    int lr = lane >> 2;
    int lc = (lane & 3) << 1;
    #pragma unroll
    for (int mf = 0; mf < 4; mf++) {
        int row0 = nodeBase + warpM + mf * 16 + lr;
        int row1 = row0 + 8;
        #pragma unroll
        for (int nf = 0; nf < 4; nf++) {
            int col = warpN + nf * 8 + lc;
            float b0 = bias[col], b1 = bias[col + 1];
            if (row0 < N_NODES)
                *(float2*)(out + (size_t)row0 * F + col)
                    = make_float2(fmaxf(acc[mf][nf][0] + b0, 0.f),
                                  fmaxf(acc[mf][nf][1] + b1, 0.f));
            if (row1 < N_NODES)
                *(float2*)(out + (size_t)row1 * F + col)
                    = make_float2(fmaxf(acc[mf][nf][2] + b0, 0.f),
                                  fmaxf(acc[mf][nf][3] + b1, 0.f));
        }
    }
}

// ---------------- launch ---------------------------------------------------
extern "C" void kernel_launch(void* const* d_in, const int* in_sizes, int n_in,
                              void* d_out, int out_size)
{
    const float* h      = (const float*)d_in[0];
    const float* weight = (const float*)d_in[1];
    const float* gate_w = (const float*)d_in[2];
    const float* h_bias = (const float*)d_in[3];
    const float* loop_w = (const float*)d_in[4];
    const float* norm   = (const float*)d_in[5];
    const int*   src    = (const int*)d_in[6];
    const int*   dst    = (const int*)d_in[7];
    const int*   rel    = (const int*)d_in[8];
    float* out = (float*)d_out;

    // CSR build over dst (g_cnt is zero: static init on first call,
    // re-zeroed by fill_k at the end of every call)
    count_k<<<(N_EDGES + 255) / 256, 256>>>(dst);
    scan1_k<<<SCAN_NB, SCAN_BLK>>>();
    scan2_k<<<1, 128>>>();
    scan3_k<<<SCAN_NB, SCAN_BLK>>>();
    fill_k<<<(N_EDGES + 255) / 256, 256>>>(dst);

    // gate values
    gate_k<<<(N_NODES * 32) / 256, 256>>>(h, gate_w);

    // aggregate-first: build virtual A rows (fp16), incl. h block + padding
    aggA_k<<<N_PAD / 8, 256>>>(h, norm, src, rel);

    // B^T fp16
    convB_k<<<(F * KTOT + 255) / 256, 256>>>(weight, loop_w);

    // fused single-pass fp16 GEMM + bias + ReLU
    cudaFuncSetAttribute(gemm_k, cudaFuncAttributeMaxDynamicSharedMemorySize,
                         GEMM_SMEM);
    gemm_k<<<N_PAD / 128, 256, GEMM_SMEM>>>(h_bias, out);
}